// round 16
// baseline (speedup 1.0000x reference)
#include <cuda_runtime.h>

// NeuralCDE: B=1024 RK4(3/8) recurrences, 127 steps, 4 F-evals/step.
// 147 CTAs x 512 threads (4 warps/SMSP for latency hiding), 7 rows per CTA.
// mm2: fma.rn.f32x2, K packed into lanes; 2 cols/thread; W2 staged per k-pair as
//      [kp][c>>1][{c0k0,c0k1,c1k0,c1k1}] -> one clean LDS.128 per k-pair.
// mm1: warp owns 4 cols x 8 rows -> W1 read once per CTA, 1-wavefront accesses.
// Phase structure identical to the 2150us winner (no fusion -- ptxas rule).

#define NB   1024
#define NT   128
#define NI   16
#define NHID 64
#define NOUT 10
#define MR   7
#define NCTA 147
#define NTHR 512
#define KSM  44             // W2 rows held in SMEM (22 k-pairs)
#define KRG  20             // W2 rows held in registers (10 k-pairs)
#define NQS  (KSM / 4)      // 11 quad iterations (2 k-pairs each)
#define NQR  (KRG / 4)      // 5
#define ZP   68             // padded row stride for z / zp_ / w1t
#define HP   68             // padded row stride for h (conflict-free stores)

struct __align__(16) SM {
    float w2[KSM * 1024];   // 180224 B  [kp][cpair][{c0k0,c0k1,c1k0,c1k1}]
    float w1t[64 * ZP];     //  17408 B  [col][k] padded
    float b2[1024];         //   4096 B
    float wlin[640];        //   2560 B
    float blin[16];         //     64 B
    float b1[64];           //    256 B
    float z[8 * ZP];        //   2176 B  [row][k] padded (row 7 unused/garbage)
    float zp_[8 * ZP];      //   2176 B
    float ks[4][512];       //   8192 B  [ss][row*64+hid] (also W_init scratch at init)
    float h[8 * HP];        //   2176 B  [row][k] padded
    float dx[4 * 8 * 16];   //   2048 B  [substep][row][ch]
};                          // total ~221376 B (<= 232448 max dyn smem)

static __device__ __forceinline__ unsigned long long pk(float a, float b) {
    unsigned long long r;
    asm("mov.b64 %0, {%1, %2};" : "=l"(r) : "f"(a), "f"(b));
    return r;
}
static __device__ __forceinline__ void upk(unsigned long long u, float& a, float& b) {
    asm("mov.b64 {%0, %1}, %2;" : "=f"(a), "=f"(b) : "l"(u));
}
static __device__ __forceinline__ void fma2(unsigned long long& d,
                                            unsigned long long a,
                                            unsigned long long b) {
    asm("fma.rn.f32x2 %0, %1, %2, %0;" : "+l"(d) : "l"(a), "l"(b));
}
// tanh(x) = 1 - 2/(exp(2x)+1); ex2/rcp approx -> ~1e-6 abs err, saturates correctly.
static __device__ __forceinline__ float tanh_fast(float x) {
    float e, r;
    asm("ex2.approx.f32 %0, %1;" : "=f"(e) : "f"(x * 2.8853900817779268f));
    asm("rcp.approx.f32 %0, %1;" : "=f"(r) : "f"(e + 1.0f));
    return fmaf(-2.0f, r, 1.0f);
}

__global__ void __launch_bounds__(NTHR, 1)
cde_kernel(const float* __restrict__ ca, const float* __restrict__ cb,
           const float* __restrict__ cc, const float* __restrict__ cd,
           const float* __restrict__ Wi, const float* __restrict__ bi,
           const float* __restrict__ W1, const float* __restrict__ b1g,
           const float* __restrict__ W2, const float* __restrict__ b2g,
           const float* __restrict__ Wl, const float* __restrict__ blg,
           float* __restrict__ out) {
    extern __shared__ __align__(16) char smraw[];
    SM* s = (SM*)smraw;
    const int t  = threadIdx.x;
    const int b0 = (blockIdx.x == NCTA - 1) ? (NB - MR) : blockIdx.x * MR;

    // ---- W2 register tail: rows 44..63, this thread's 2 cols (2t, 2t+1), k-paired ----
    unsigned long long wr[KRG / 2][2];
#pragma unroll
    for (int p = 0; p < KRG / 2; p++) {
        float2 a = *(const float2*)(W2 + (size_t)(KSM + 2 * p) * 1024 + 2 * t);
        float2 b = *(const float2*)(W2 + (size_t)(KSM + 2 * p + 1) * 1024 + 2 * t);
        wr[p][0] = pk(a.x, b.x);
        wr[p][1] = pk(a.y, b.y);
    }
    // ---- stage weights into SMEM ----
    {
        // W2 rows 0..43 -> [kp][cpair]: dst = kp*2048 + 8*q + (k&1); d[0,2,4,6] = cols 4q..4q+3
        for (int i = t; i < KSM * 256; i += NTHR) {
            int k = i >> 8, q = i & 255;
            float4 v = ((const float4*)W2)[i];
            float* d = s->w2 + (k >> 1) * 2048 + q * 8 + (k & 1);
            d[0] = v.x;  d[2] = v.y;  d[4] = v.z;  d[6] = v.w;
        }
        // W1 transposed padded: w1t[c*ZP + k] = W1[k][c]
        for (int i = t; i < 4096; i += NTHR) {
            int k = i >> 6, c = i & 63;
            s->w1t[c * ZP + k] = W1[i];
        }
        if (t < 256) ((float4*)s->b2)[t] = ((const float4*)b2g)[t];
        if (t < 160) ((float4*)s->wlin)[t] = ((const float4*)Wl)[t];
        if (t < NOUT) s->blin[t] = blg[t];
        if (t < 64) s->b1[t] = b1g[t];
        // W_init (1024 floats) into ks scratch
        if (t < 256) ((float4*)s->ks[0])[t] = ((const float4*)Wi)[t];
        // coeff_a[:,0] (7x16) into dx[0] scratch
        if (t < MR * 16) {
            int r = t >> 4, i = t & 15;
            s->dx[r * 16 + i] = ca[((size_t)(b0 + r) * 127 + 0) * 16 + i];
        }
    }
    __syncthreads();

    // ---- z0 = coeff_a[:,0] @ W_init + b_init (7x64 = 448 elems, 1/thread) ----
    if (t < MR * 64) {
        int r = t >> 6, hid = t & 63;
        float a = bi[hid];
#pragma unroll
        for (int i = 0; i < 16; i++)
            a = fmaf(s->dx[r * 16 + i], s->ks[0][i * 64 + hid], a);
        s->z[r * ZP + hid] = a;
    }
    __syncthreads();

    // ---- coeff prefetch registers (threads 256..367) ----
    const bool is_dx = (t >= 256) && (t < 256 + MR * 16);
    float pf_b = 0.0f, pf_c = 0.0f, pf_d = 0.0f;
    size_t pf_base = 0;
    if (is_dx) {
        int q = t - 256;
        pf_base = ((size_t)(b0 + (q >> 4)) * 127) * 16 + (q & 15);
        pf_b = cb[pf_base]; pf_c = cc[pf_base]; pf_d = cd[pf_base];
    }

    // ================= main time loop =================
    for (int j = 0; j < NT - 1; j++) {
        // Phase A: dX build from prefetched coeffs; low threads emit output row j.
        if (is_dx) {
            int q = t - 256;
            int r = q >> 4, i = q & 15;
            float bb = pf_b, c2 = pf_c, d3 = pf_d;
            float old3 = s->dx[(3 * 8 + r) * 16 + i];
            float fj = (float)j;
            float f1 = (fj + (1.0f / 3.0f)) - fj;   // matches reference fp32 frac
            float f2 = (fj + (2.0f / 3.0f)) - fj;
            s->dx[(0 * 8 + r) * 16 + i] = (j == 0) ? bb : old3;  // k1: prev interval, frac=1
            s->dx[(1 * 8 + r) * 16 + i] = fmaf(fmaf(d3, f1, c2), f1, bb);
            s->dx[(2 * 8 + r) * 16 + i] = fmaf(fmaf(d3, f2, c2), f2, bb);
            s->dx[(3 * 8 + r) * 16 + i] = bb + (c2 + d3);        // frac=1
        } else if (t < MR * NOUT) {
            int r = t / 10, o = t % 10;
            float a = s->blin[o];
#pragma unroll 8
            for (int kk = 0; kk < 64; kk++) a = fmaf(s->z[r * ZP + kk], s->wlin[kk * 10 + o], a);
            out[((size_t)(b0 + r) * NT + j) * NOUT + o] = a;
        }
        __syncthreads();
        // issue next step's coeff loads; latency drains under the 4 substeps
        if (is_dx && j + 1 < NT - 1) {
            size_t base = pf_base + (size_t)(j + 1) * 16;
            pf_b = cb[base]; pf_c = cc[base]; pf_d = cd[base];
        }

        // ---- four RK4(3/8) substeps ----
#pragma unroll 1
        for (int ss = 0; ss < 4; ss++) {
            const float* zin = s->z;
            if (ss > 0) {
                if (t < MR * 64) {
                    int r = t >> 6, kk = t & 63;
                    float zv = s->z[r * ZP + kk];
                    float v;
                    if (ss == 1)      v = fmaf(s->ks[0][t], (1.0f / 3.0f), zv);
                    else if (ss == 2) v = zv + s->ks[1][t] - s->ks[0][t] * (1.0f / 3.0f);
                    else              v = zv + s->ks[0][t] - s->ks[1][t] + s->ks[2][t];
                    s->zp_[r * ZP + kk] = v;
                }
                __syncthreads();
                zin = s->zp_;
            }
            // ---- mm1: warp w -> cols 4w..4w+3; lane = (col = lane&3, row = lane>>2) ----
            {
                int w = t >> 5, lane = t & 31;
                int c = (w << 2) + (lane & 3);
                int r = lane >> 2;                  // 0..7; row 7 garbage, store-guarded
                const float* zr = zin + r * ZP;
                const float* wc = s->w1t + c * ZP;
                float a0 = s->b1[c];
#pragma unroll
                for (int q = 0; q < 16; q++) {
                    float4 wq = *(const float4*)(wc + 4 * q);
                    float4 z0 = *(const float4*)(zr + 4 * q);
                    a0 = fmaf(z0.x, wq.x, a0); a0 = fmaf(z0.y, wq.y, a0);
                    a0 = fmaf(z0.z, wq.z, a0); a0 = fmaf(z0.w, wq.w, a0);
                }
                if (r < MR) s->h[r * HP + c] = fmaxf(a0, 0.0f);
            }
            __syncthreads();

            // ---- mm2: g = h @ W2 + b2, cols 2t..2t+1, 7 rows ----
            unsigned long long acc[2][MR];
            {
                float2 bv = *(const float2*)(s->b2 + 2 * t);
                unsigned long long q0 = pk(bv.x, 0.0f), q1 = pk(bv.y, 0.0f);
#pragma unroll
                for (int r = 0; r < MR; r++) { acc[0][r] = q0; acc[1][r] = q1; }
            }
#pragma unroll 2
            for (int kq = 0; kq < NQS; kq++) {
                const float* wp = s->w2 + (size_t)(2 * kq) * 2048 + 4 * t;
                ulonglong2 wv0 = *(const ulonglong2*)(wp);          // k-pair 2kq:   {c0,c1}
                ulonglong2 wv1 = *(const ulonglong2*)(wp + 2048);   // k-pair 2kq+1: {c0,c1}
#pragma unroll
                for (int r = 0; r < MR; r++) {
                    ulonglong2 hv = *(const ulonglong2*)(s->h + r * HP + 4 * kq);
                    fma2(acc[0][r], hv.x, wv0.x);
                    fma2(acc[1][r], hv.x, wv0.y);
                    fma2(acc[0][r], hv.y, wv1.x);
                    fma2(acc[1][r], hv.y, wv1.y);
                }
            }
            // register tail: rows 44..63, zero smem w-traffic
#pragma unroll
            for (int qq = 0; qq < NQR; qq++) {
                const int p0 = 2 * qq, p1i = 2 * qq + 1;
#pragma unroll
                for (int r = 0; r < MR; r++) {
                    ulonglong2 hv = *(const ulonglong2*)(s->h + r * HP + KSM + 4 * qq);
                    fma2(acc[0][r], hv.x, wr[p0][0]);
                    fma2(acc[1][r], hv.x, wr[p0][1]);
                    fma2(acc[0][r], hv.y, wr[p1i][0]);
                    fma2(acc[1][r], hv.y, wr[p1i][1]);
                }
            }
            // ---- epilogue: fold lanes + tanh + einsum with dX + 8-lane reduce ----
            {
                int i0 = (t & 7) * 2, hc = t >> 3;   // cols 2t,2t+1 = hid hc, ch i0,i0+1
#pragma unroll
                for (int r = 0; r < MR; r++) {
                    float2 dxv = *(const float2*)(s->dx + (ss * 8 + r) * 16 + i0);
                    float e0, o0, e1, o1;
                    upk(acc[0][r], e0, o0);
                    upk(acc[1][r], e1, o1);
                    float p = tanh_fast(e0 + o0) * dxv.x + tanh_fast(e1 + o1) * dxv.y;
                    p += __shfl_xor_sync(0xffffffffu, p, 1);
                    p += __shfl_xor_sync(0xffffffffu, p, 2);
                    p += __shfl_xor_sync(0xffffffffu, p, 4);
                    if ((t & 7) == 0) s->ks[ss][r * 64 + hc] = p;
                }
            }
            __syncthreads();
        }
        // ---- zn = z + (k1 + 3(k2+k3) + k4)/8 (1 elem/thread) ----
        if (t < MR * 64) {
            int r = t >> 6, kk = t & 63;
            float d = s->ks[0][t] + 3.0f * (s->ks[1][t] + s->ks[2][t]) + s->ks[3][t];
            s->z[r * ZP + kk] = fmaf(d, 0.125f, s->z[r * ZP + kk]);
        }
        __syncthreads();
    }
    // ---- final output row t = 127 ----
    if (t < MR * NOUT) {
        int r = t / 10, o = t % 10;
        float a = s->blin[o];
#pragma unroll 8
        for (int kk = 0; kk < 64; kk++) a = fmaf(s->z[r * ZP + kk], s->wlin[kk * 10 + o], a);
        out[((size_t)(b0 + r) * NT + (NT - 1)) * NOUT + o] = a;
    }
}

extern "C" void kernel_launch(void* const* d_in, const int* in_sizes, int n_in,
                              void* d_out, int out_size) {
    // metadata order: times, coeff_a, coeff_b, coeff_two_c, coeff_three_d,
    //                 final_index, W_init, b_init, W1, b1, W2, b2, W_lin, b_lin
    const float* ca = (const float*)d_in[1];
    const float* cb = (const float*)d_in[2];
    const float* cc = (const float*)d_in[3];
    const float* cd = (const float*)d_in[4];
    const float* Wi = (const float*)d_in[6];
    const float* bi = (const float*)d_in[7];
    const float* W1 = (const float*)d_in[8];
    const float* b1 = (const float*)d_in[9];
    const float* W2 = (const float*)d_in[10];
    const float* b2 = (const float*)d_in[11];
    const float* Wl = (const float*)d_in[12];
    const float* bl = (const float*)d_in[13];
    float* out = (float*)d_out;

    size_t smem = sizeof(SM);
    cudaFuncSetAttribute(cde_kernel, cudaFuncAttributeMaxDynamicSharedMemorySize, (int)smem);
    cde_kernel<<<NCTA, NTHR, smem>>>(ca, cb, cc, cd, Wi, bi, W1, b1, W2, b2, Wl, bl, out);
}

// round 17
// speedup vs baseline: 1.2045x; 1.2045x over previous
#include <cuda_runtime.h>

// NeuralCDE: B=1024 RK4(3/8) recurrences, 127 steps, 4 F-evals/step.
// 147 CTAs x 256 threads (one per SM), 7 batch rows per CTA (last CTA overlaps).
// mm2: fma.rn.f32x2, K packed into lanes; W2 conflict-free k-pair layout + reg tail.
// mm1: f32x2 ROW-pairing -- rows {pr, pr+4} in the two FFMA2 lanes (64 instr vs 128),
//      fed by zpair[4][66] float2 (pr-padded, conflict-free). W1 read once per CTA.
// Phase structure identical to the 2149.6us winner (no fusion -- ptxas rule).

#define NB   1024
#define NT   128
#define NI   16
#define NHID 64
#define NOUT 10
#define MR   7
#define NCTA 147
#define NTHR 256
#define KSM  44             // W2 rows held in SMEM (22 k-pairs)
#define KRG  20             // W2 rows held in registers (10 k-pairs)
#define NQS  (KSM / 4)      // 11 quad iterations (2 k-pairs each)
#define NQR  (KRG / 4)      // 5
#define ZP   68             // padded row stride for z / w1t
#define HP   68             // padded row stride for h (conflict-free stores)
#define PRS  66             // zpair per-pr stride in float2 (pad -> banks 0/4/8/12)

struct __align__(16) SM {
    float w2[KSM * 1024];   // 180224 B  [kp][half][t][{c0k0,c0k1,c1k0,c1k1}]
    float w1t[64 * ZP];     //  17408 B  [col][k] padded
    float b2[1024];         //   4096 B
    float wlin[640];        //   2560 B
    float blin[16];         //     64 B
    float b1[64];           //    256 B
    float z[8 * ZP];        //   2176 B  [row][k] padded (row 7 unused/garbage)
    float zpair[4 * PRS * 2]; // 2112 B  float2 (pr,k) = {z'[pr][k], z'[pr+4][k]}
    float ks[4][512];       //   8192 B  [ss][row*64+hid] (also W_init scratch at init)
    float h[8 * HP];        //   2176 B  [row][k] padded
    float dx[4 * 8 * 16];   //   2048 B  [substep][row][ch]
};                          // total ~221312 B (<= 232448 max dyn smem)

static __device__ __forceinline__ unsigned long long pk(float a, float b) {
    unsigned long long r;
    asm("mov.b64 %0, {%1, %2};" : "=l"(r) : "f"(a), "f"(b));
    return r;
}
static __device__ __forceinline__ void upk(unsigned long long u, float& a, float& b) {
    asm("mov.b64 {%0, %1}, %2;" : "=f"(a), "=f"(b) : "l"(u));
}
static __device__ __forceinline__ void fma2(unsigned long long& d,
                                            unsigned long long a,
                                            unsigned long long b) {
    asm("fma.rn.f32x2 %0, %1, %2, %0;" : "+l"(d) : "l"(a), "l"(b));
}
// tanh(x) = 1 - 2/(exp(2x)+1); ex2/rcp approx -> ~1e-6 abs err, saturates correctly.
static __device__ __forceinline__ float tanh_fast(float x) {
    float e, r;
    asm("ex2.approx.f32 %0, %1;" : "=f"(e) : "f"(x * 2.8853900817779268f));
    asm("rcp.approx.f32 %0, %1;" : "=f"(r) : "f"(e + 1.0f));
    return fmaf(-2.0f, r, 1.0f);
}

__global__ void __launch_bounds__(NTHR, 1)
cde_kernel(const float* __restrict__ ca, const float* __restrict__ cb,
           const float* __restrict__ cc, const float* __restrict__ cd,
           const float* __restrict__ Wi, const float* __restrict__ bi,
           const float* __restrict__ W1, const float* __restrict__ b1g,
           const float* __restrict__ W2, const float* __restrict__ b2g,
           const float* __restrict__ Wl, const float* __restrict__ blg,
           float* __restrict__ out) {
    extern __shared__ __align__(16) char smraw[];
    SM* s = (SM*)smraw;
    const int t  = threadIdx.x;
    const int b0 = (blockIdx.x == NCTA - 1) ? (NB - MR) : blockIdx.x * MR;

    // ---- W2 register tail: rows 44..63, this thread's 4 cols (4t..4t+3), k-paired ----
    unsigned long long wr[KRG / 2][4];
#pragma unroll
    for (int p = 0; p < KRG / 2; p++) {
        float4 a = *(const float4*)(W2 + (size_t)(KSM + 2 * p) * 1024 + 4 * t);
        float4 b = *(const float4*)(W2 + (size_t)(KSM + 2 * p + 1) * 1024 + 4 * t);
        wr[p][0] = pk(a.x, b.x);
        wr[p][1] = pk(a.y, b.y);
        wr[p][2] = pk(a.z, b.z);
        wr[p][3] = pk(a.w, b.w);
    }
    // ---- stage weights into SMEM ----
    {
        // W2 rows 0..43: per k-pair kp = k>>1, two 4KB halves, 16B per thread per half.
        for (int i = t; i < KSM * 256; i += NTHR) {
            int k = i >> 8, q = i & 255;
            float4 v = ((const float4*)W2)[i];
            float* d = s->w2 + (k >> 1) * 2048 + q * 4 + (k & 1);
            d[0]    = v.x;  d[2]    = v.y;
            d[1024] = v.z;  d[1026] = v.w;
        }
        // W1 transposed padded: w1t[c*ZP + k] = W1[k][c]
        for (int i = t; i < 4096; i += NTHR) {
            int k = i >> 6, c = i & 63;
            s->w1t[c * ZP + k] = W1[i];
        }
        ((float4*)s->b2)[t] = ((const float4*)b2g)[t];
        if (t < 160) ((float4*)s->wlin)[t] = ((const float4*)Wl)[t];
        if (t < NOUT) s->blin[t] = blg[t];
        if (t < 64) s->b1[t] = b1g[t];
        // W_init (1024 floats) into ks scratch
        ((float4*)s->ks[0])[t] = ((const float4*)Wi)[t];
        // coeff_a[:,0] (7x16) into dx[0] scratch
        if (t < MR * 16) {
            int r = t >> 4, i = t & 15;
            s->dx[r * 16 + i] = ca[((size_t)(b0 + r) * 127 + 0) * 16 + i];
        }
    }
    __syncthreads();

    // ---- z0 = coeff_a[:,0] @ W_init + b_init (7x64 = 448 elems) ----
#pragma unroll
    for (int e = 0; e < 2; e++) {
        int idx = t + e * 256;
        if (idx < MR * 64) {
            int r = idx >> 6, hid = idx & 63;
            float a = bi[hid];
#pragma unroll
            for (int i = 0; i < 16; i++)
                a = fmaf(s->dx[r * 16 + i], s->ks[0][i * 64 + hid], a);
            s->z[r * ZP + hid] = a;
        }
    }
    __syncthreads();
    // ---- fill zpair with z0 (pr pairs rows pr, pr+4; row 7 garbage, discarded) ----
    {
        int pr = t >> 6, k = t & 63;
        float a = s->z[pr * ZP + k];
        float b = s->z[(pr + 4) * ZP + k];
        *(float2*)(s->zpair + (pr * PRS + k) * 2) = make_float2(a, b);
    }

    // ---- coeff prefetch registers (valid on threads 128..239) ----
    const bool is_dx = (t >= 128) && (t < 128 + MR * 16);
    float pf_b = 0.0f, pf_c = 0.0f, pf_d = 0.0f;
    size_t pf_base = 0;
    if (is_dx) {
        int q = t - 128;
        pf_base = ((size_t)(b0 + (q >> 4)) * 127) * 16 + (q & 15);
        pf_b = cb[pf_base]; pf_c = cc[pf_base]; pf_d = cd[pf_base];
    }
    __syncthreads();

    // ================= main time loop =================
    for (int j = 0; j < NT - 1; j++) {
        // Phase A: dX build from prefetched coeffs; low threads emit output row j.
        if (is_dx) {
            int q = t - 128;
            int r = q >> 4, i = q & 15;
            float bb = pf_b, c2 = pf_c, d3 = pf_d;
            float old3 = s->dx[(3 * 8 + r) * 16 + i];
            float fj = (float)j;
            float f1 = (fj + (1.0f / 3.0f)) - fj;   // matches reference fp32 frac
            float f2 = (fj + (2.0f / 3.0f)) - fj;
            s->dx[(0 * 8 + r) * 16 + i] = (j == 0) ? bb : old3;  // k1: prev interval, frac=1
            s->dx[(1 * 8 + r) * 16 + i] = fmaf(fmaf(d3, f1, c2), f1, bb);
            s->dx[(2 * 8 + r) * 16 + i] = fmaf(fmaf(d3, f2, c2), f2, bb);
            s->dx[(3 * 8 + r) * 16 + i] = bb + (c2 + d3);        // frac=1
        } else if (t < MR * NOUT) {
            int r = t / 10, o = t % 10;
            float a = s->blin[o];
#pragma unroll 8
            for (int kk = 0; kk < 64; kk++) a = fmaf(s->z[r * ZP + kk], s->wlin[kk * 10 + o], a);
            out[((size_t)(b0 + r) * NT + j) * NOUT + o] = a;
        }
        __syncthreads();
        // issue next step's coeff loads; latency drains under the 4 substeps
        if (is_dx && j + 1 < NT - 1) {
            size_t base = pf_base + (size_t)(j + 1) * 16;
            pf_b = cb[base]; pf_c = cc[base]; pf_d = cd[base];
        }

        // ---- four RK4(3/8) substeps ----
#pragma unroll 1
        for (int ss = 0; ss < 4; ss++) {
            if (ss > 0) {
                // zp: z' for rows (pr, pr+4) -> zpair only (mm1 is sole consumer)
                int pr = t >> 6, k = t & 63;
                int i0 = pr * 64 + k, i1 = i0 + 256;   // i1 row 7 for pr=3: garbage, discarded
                float zv0 = s->z[pr * ZP + k];
                float zv1 = s->z[(pr + 4) * ZP + k];
                float v0, v1;
                if (ss == 1) {
                    v0 = fmaf(s->ks[0][i0], (1.0f / 3.0f), zv0);
                    v1 = fmaf(s->ks[0][i1], (1.0f / 3.0f), zv1);
                } else if (ss == 2) {
                    v0 = zv0 + s->ks[1][i0] - s->ks[0][i0] * (1.0f / 3.0f);
                    v1 = zv1 + s->ks[1][i1] - s->ks[0][i1] * (1.0f / 3.0f);
                } else {
                    v0 = zv0 + s->ks[0][i0] - s->ks[1][i0] + s->ks[2][i0];
                    v1 = zv1 + s->ks[0][i1] - s->ks[1][i1] + s->ks[2][i1];
                }
                *(float2*)(s->zpair + (pr * PRS + k) * 2) = make_float2(v0, v1);
                __syncthreads();
            }
            // ---- mm1 (f32x2 row-paired): warp w -> cols 8w..8w+7, lane pr = rows (pr, pr+4) ----
            {
                int w = t >> 5, lane = t & 31;
                int c = (w << 3) + (lane & 7);
                int pr = lane >> 3;                 // 0..3; lane .y = row pr+4 (pr=3 -> garbage)
                const unsigned long long* zz =
                    (const unsigned long long*)s->zpair + pr * PRS;
                const float* wc = s->w1t + c * ZP;
                unsigned long long ap = pk(s->b1[c], s->b1[c]);
#pragma unroll
                for (int q = 0; q < 16; q++) {
                    float4 wq = *(const float4*)(wc + 4 * q);
                    ulonglong2 zA = *(const ulonglong2*)(zz + 4 * q);
                    ulonglong2 zB = *(const ulonglong2*)(zz + 4 * q + 2);
                    fma2(ap, zA.x, pk(wq.x, wq.x));
                    fma2(ap, zA.y, pk(wq.y, wq.y));
                    fma2(ap, zB.x, pk(wq.z, wq.z));
                    fma2(ap, zB.y, pk(wq.w, wq.w));
                }
                float a0, a1;
                upk(ap, a0, a1);
                s->h[pr * HP + c] = fmaxf(a0, 0.0f);
                if (pr < MR - 4) s->h[(pr + 4) * HP + c] = fmaxf(a1, 0.0f);
            }
            __syncthreads();

            // ---- mm2: g = h @ W2 + b2, cols 4t..4t+3, 7 rows ----
            unsigned long long acc[4][MR];
            {
                float4 bv = *(const float4*)(s->b2 + 4 * t);
                unsigned long long q0 = pk(bv.x, 0.0f), q1 = pk(bv.y, 0.0f);
                unsigned long long q2 = pk(bv.z, 0.0f), q3 = pk(bv.w, 0.0f);
#pragma unroll
                for (int r = 0; r < MR; r++) {
                    acc[0][r] = q0; acc[1][r] = q1; acc[2][r] = q2; acc[3][r] = q3;
                }
            }
#pragma unroll 2
            for (int kq = 0; kq < NQS; kq++) {
                const float* wp = s->w2 + (size_t)(2 * kq) * 2048 + 4 * t;
                ulonglong2 wA = *(const ulonglong2*)(wp);          // kp0: cols 0,1
                ulonglong2 wB = *(const ulonglong2*)(wp + 1024);   // kp0: cols 2,3
                ulonglong2 wC = *(const ulonglong2*)(wp + 2048);   // kp1: cols 0,1
                ulonglong2 wD = *(const ulonglong2*)(wp + 3072);   // kp1: cols 2,3
#pragma unroll
                for (int r = 0; r < MR; r++) {
                    ulonglong2 hv = *(const ulonglong2*)(s->h + r * HP + 4 * kq);
                    fma2(acc[0][r], hv.x, wA.x);
                    fma2(acc[1][r], hv.x, wA.y);
                    fma2(acc[2][r], hv.x, wB.x);
                    fma2(acc[3][r], hv.x, wB.y);
                    fma2(acc[0][r], hv.y, wC.x);
                    fma2(acc[1][r], hv.y, wC.y);
                    fma2(acc[2][r], hv.y, wD.x);
                    fma2(acc[3][r], hv.y, wD.y);
                }
            }
            // register tail: rows 44..63, zero smem w-traffic
#pragma unroll
            for (int qq = 0; qq < NQR; qq++) {
                const int p0 = 2 * qq, p1i = 2 * qq + 1;
#pragma unroll
                for (int r = 0; r < MR; r++) {
                    ulonglong2 hv = *(const ulonglong2*)(s->h + r * HP + KSM + 4 * qq);
                    fma2(acc[0][r], hv.x, wr[p0][0]);
                    fma2(acc[1][r], hv.x, wr[p0][1]);
                    fma2(acc[2][r], hv.x, wr[p0][2]);
                    fma2(acc[3][r], hv.x, wr[p0][3]);
                    fma2(acc[0][r], hv.y, wr[p1i][0]);
                    fma2(acc[1][r], hv.y, wr[p1i][1]);
                    fma2(acc[2][r], hv.y, wr[p1i][2]);
                    fma2(acc[3][r], hv.y, wr[p1i][3]);
                }
            }
            // ---- epilogue: fold lanes + tanh + einsum with dX + 4-lane reduce ----
            {
                int i0 = (t & 3) * 4, hc = t >> 2;
#pragma unroll
                for (int r = 0; r < MR; r++) {
                    float4 dxv = *(const float4*)(s->dx + (ss * 8 + r) * 16 + i0);
                    float e0, o0, e1, o1, e2, o2, e3, o3;
                    upk(acc[0][r], e0, o0);
                    upk(acc[1][r], e1, o1);
                    upk(acc[2][r], e2, o2);
                    upk(acc[3][r], e3, o3);
                    float p = tanh_fast(e0 + o0) * dxv.x + tanh_fast(e1 + o1) * dxv.y
                            + tanh_fast(e2 + o2) * dxv.z + tanh_fast(e3 + o3) * dxv.w;
                    p += __shfl_xor_sync(0xffffffffu, p, 1);
                    p += __shfl_xor_sync(0xffffffffu, p, 2);
                    if ((t & 3) == 0) s->ks[ss][r * 64 + hc] = p;
                }
            }
            __syncthreads();
        }
        // ---- zn: rows (pr, pr+4); scalar z (for output/zp) + zpair (for ss=0 mm1) ----
        {
            int pr = t >> 6, k = t & 63;
            int i0 = pr * 64 + k, i1 = i0 + 256;   // i1 row 7 for pr=3: garbage, discarded
            float d0 = s->ks[0][i0] + 3.0f * (s->ks[1][i0] + s->ks[2][i0]) + s->ks[3][i0];
            float d1 = s->ks[0][i1] + 3.0f * (s->ks[1][i1] + s->ks[2][i1]) + s->ks[3][i1];
            float z0n = fmaf(d0, 0.125f, s->z[pr * ZP + k]);
            float z1n = fmaf(d1, 0.125f, s->z[(pr + 4) * ZP + k]);
            s->z[pr * ZP + k] = z0n;
            s->z[(pr + 4) * ZP + k] = z1n;         // row 7 garbage store, never read
            *(float2*)(s->zpair + (pr * PRS + k) * 2) = make_float2(z0n, z1n);
        }
        __syncthreads();
    }
    // ---- final output row t = 127 ----
    if (t < MR * NOUT) {
        int r = t / 10, o = t % 10;
        float a = s->blin[o];
#pragma unroll 8
        for (int kk = 0; kk < 64; kk++) a = fmaf(s->z[r * ZP + kk], s->wlin[kk * 10 + o], a);
        out[((size_t)(b0 + r) * NT + (NT - 1)) * NOUT + o] = a;
    }
}

extern "C" void kernel_launch(void* const* d_in, const int* in_sizes, int n_in,
                              void* d_out, int out_size) {
    // metadata order: times, coeff_a, coeff_b, coeff_two_c, coeff_three_d,
    //                 final_index, W_init, b_init, W1, b1, W2, b2, W_lin, b_lin
    const float* ca = (const float*)d_in[1];
    const float* cb = (const float*)d_in[2];
    const float* cc = (const float*)d_in[3];
    const float* cd = (const float*)d_in[4];
    const float* Wi = (const float*)d_in[6];
    const float* bi = (const float*)d_in[7];
    const float* W1 = (const float*)d_in[8];
    const float* b1 = (const float*)d_in[9];
    const float* W2 = (const float*)d_in[10];
    const float* b2 = (const float*)d_in[11];
    const float* Wl = (const float*)d_in[12];
    const float* bl = (const float*)d_in[13];
    float* out = (float*)d_out;

    size_t smem = sizeof(SM);
    cudaFuncSetAttribute(cde_kernel, cudaFuncAttributeMaxDynamicSharedMemorySize, (int)smem);
    cde_kernel<<<NCTA, NTHR, smem>>>(ca, cb, cc, cd, Wi, bi, W1, b1, W2, b2, Wl, bl, out);
}